// round 14
// baseline (speedup 1.0000x reference)
#include <cuda_runtime.h>

#define BB   32
#define NN   2048
#define KK   16
#define FIN  32
#define FOUT 64
#define NPTS (BB * NN)          // 65536
#define PAD  4
#define NS   (NN + 2 * PAD)     // 2056
#define QPB  128                // queries per block
#define KNN_THREADS 512         // 4 lanes per query, in-warp quads
#define MSTR 17                 // padded per-thread mask stride (words)

// SMEM layout (bytes)
#define OFF_SP    0
#define OFF_BOX   (NS * 16)                    // 32896 : 64 boxes x 2 float4
#define OFF_MASK  (OFF_BOX + 64 * 32)          // 34944 : 512 threads x 17 words
#define OFF_CNT   (OFF_MASK + KNN_THREADS * MSTR * 4)   // 69760
#define KNN_SMEM  (OFF_CNT + QPB * 4)          // 70272

// Scratch (allocation-free rule: __device__ globals)
__device__ float4 g_sorted[BB * NS];
__device__ float  g_a[NPTS * FOUT];
__device__ float  g_c[NPTS * FOUT];
__device__ float  g_s[NPTS * FOUT];
__device__ int    g_idx[NPTS * KK];

// ---------------------------------------------------------------------------
__device__ __forceinline__ unsigned spread3(unsigned x) {
    x &= 0x3FF;
    x = (x | (x << 16)) & 0x030000FF;
    x = (x | (x << 8))  & 0x0300F00F;
    x = (x | (x << 4))  & 0x030C30C3;
    x = (x | (x << 2))  & 0x09249249;
    return x;
}

// ---------------------------------------------------------------------------
// Kernel 0: per-batch Morton sort (7 bits/dim). Bitonic on packed uint32 keys.
// ---------------------------------------------------------------------------
__global__ __launch_bounds__(1024) void sort_kernel(const float* __restrict__ pos) {
    __shared__ float4   spp[NN];
    __shared__ unsigned key[NN];
    __shared__ float    s_red[6][32];
    __shared__ float    s_bounds[6];

    const int b    = blockIdx.x;
    const int tid  = threadIdx.x;
    const int lane = tid & 31;
    const int wid  = tid >> 5;

    for (int i = tid; i < NN; i += 1024) {
        const float* p = pos + (size_t)(b * NN + i) * 3;
        spp[i] = make_float4(p[0], p[1], p[2], __int_as_float(i));
    }
    __syncthreads();

    float mn[3] = { 3e38f, 3e38f, 3e38f }, mx[3] = { -3e38f, -3e38f, -3e38f };
    for (int i = tid; i < NN; i += 1024) {
        float4 q = spp[i];
        mn[0] = fminf(mn[0], q.x); mx[0] = fmaxf(mx[0], q.x);
        mn[1] = fminf(mn[1], q.y); mx[1] = fmaxf(mx[1], q.y);
        mn[2] = fminf(mn[2], q.z); mx[2] = fmaxf(mx[2], q.z);
    }
#pragma unroll
    for (int o = 16; o; o >>= 1) {
#pragma unroll
        for (int d = 0; d < 3; d++) {
            mn[d] = fminf(mn[d], __shfl_xor_sync(0xFFFFFFFFu, mn[d], o));
            mx[d] = fmaxf(mx[d], __shfl_xor_sync(0xFFFFFFFFu, mx[d], o));
        }
    }
    if (lane == 0) {
#pragma unroll
        for (int d = 0; d < 3; d++) { s_red[d][wid] = mn[d]; s_red[3 + d][wid] = mx[d]; }
    }
    __syncthreads();
    if (tid < 32) {
        float v0 = s_red[0][tid], v1 = s_red[1][tid], v2 = s_red[2][tid];
        float v3 = s_red[3][tid], v4 = s_red[4][tid], v5 = s_red[5][tid];
#pragma unroll
        for (int o = 16; o; o >>= 1) {
            v0 = fminf(v0, __shfl_xor_sync(0xFFFFFFFFu, v0, o));
            v1 = fminf(v1, __shfl_xor_sync(0xFFFFFFFFu, v1, o));
            v2 = fminf(v2, __shfl_xor_sync(0xFFFFFFFFu, v2, o));
            v3 = fmaxf(v3, __shfl_xor_sync(0xFFFFFFFFu, v3, o));
            v4 = fmaxf(v4, __shfl_xor_sync(0xFFFFFFFFu, v4, o));
            v5 = fmaxf(v5, __shfl_xor_sync(0xFFFFFFFFu, v5, o));
        }
        if (tid == 0) {
            s_bounds[0] = v0; s_bounds[1] = v1; s_bounds[2] = v2;
            s_bounds[3] = 127.0f / fmaxf(v3 - v0, 1e-12f);
            s_bounds[4] = 127.0f / fmaxf(v4 - v1, 1e-12f);
            s_bounds[5] = 127.0f / fmaxf(v5 - v2, 1e-12f);
        }
    }
    __syncthreads();

    const float mnx = s_bounds[0], mny = s_bounds[1], mnz = s_bounds[2];
    const float sx = s_bounds[3], sy = s_bounds[4], sz = s_bounds[5];
    for (int i = tid; i < NN; i += 1024) {
        float4 q = spp[i];
        unsigned ux = (unsigned)min(max((int)((q.x - mnx) * sx), 0), 127);
        unsigned uy = (unsigned)min(max((int)((q.y - mny) * sy), 0), 127);
        unsigned uz = (unsigned)min(max((int)((q.z - mnz) * sz), 0), 127);
        unsigned code = spread3(ux) | (spread3(uy) << 1) | (spread3(uz) << 2);
        key[i] = (code << 11) | (unsigned)i;
    }

    for (int k = 2; k <= NN; k <<= 1) {
        for (int j = k >> 1; j > 0; j >>= 1) {
            __syncthreads();
            int l = ((tid & ~(j - 1)) << 1) | (tid & (j - 1));
            int p = l | j;
            unsigned A = key[l], Bv = key[p];
            bool asc = (l & k) == 0;
            if ((A > Bv) == asc) { key[l] = Bv; key[p] = A; }
        }
    }
    __syncthreads();

    float4* gs = g_sorted + (size_t)b * NS;
    for (int i = tid; i < NN; i += 1024) gs[PAD + i] = spp[key[i] & 0x7FF];
    if (tid < PAD) {
        gs[tid]            = make_float4(-1.0e30f, -1.0e30f, -1.0e30f, __int_as_float(0));
        gs[PAD + NN + tid] = make_float4( 1.0e30f,  1.0e30f,  1.0e30f, __int_as_float(0));
    }
}

// ---------------------------------------------------------------------------
__device__ __forceinline__ void ins16(float dk[KK], float v) {
#pragma unroll
    for (int k = 0; k < KK; k++) {
        float lo = fminf(dk[k], v);
        v = fmaxf(dk[k], v);
        dk[k] = lo;
    }
}

// Merge my ascending dk[16] with xor-partner's: keep 16 smallest, re-sorted.
// (reverse partner + elementwise min -> bitonic; clean with d=8,4,2,1.)
__device__ __forceinline__ void merge16(float dk[KK], int lanemask) {
    float o[KK];
#pragma unroll
    for (int i = 0; i < KK; i++)
        o[i] = __shfl_xor_sync(0xFFFFFFFFu, dk[KK - 1 - i], lanemask);
#pragma unroll
    for (int i = 0; i < KK; i++) dk[i] = fminf(dk[i], o[i]);
#pragma unroll
    for (int d = 8; d >= 1; d >>= 1) {
#pragma unroll
        for (int i = 0; i < KK; i++) {
            if ((i & d) == 0) {
                float lo = fminf(dk[i], dk[i | d]);
                float hi = fmaxf(dk[i], dk[i | d]);
                dk[i] = lo; dk[i | d] = hi;
            }
        }
    }
}

// ---------------------------------------------------------------------------
// Kernel 1: exact kNN. 4 lanes per query (in-warp quad); barrier-free after
// setup. Lane seg owns candidate slice {gw*32 + seg*8 .. +8} of every word.
//  A) 48-candidate Morton window split 4-ways; shuffle-merge -> exact t0.
//  B) per global word: AABB lower bound (quad-uniform predicate); survivors
//     get branchless 8-candidate slice build; bits -> SMEM (1 word / 4 gw).
//  C) walk own bits -> partial top-16; shuffle-merge -> exact tau (all lanes).
//  E) walk again, emit d2<=tau via SMEM-atomic slots (max-pool order-free).
// ---------------------------------------------------------------------------
__global__ __launch_bounds__(KNN_THREADS) void knn_kernel(int blockOff) {
    extern __shared__ unsigned char dynsmem[];
    float4*   sp    = reinterpret_cast<float4*>(dynsmem + OFF_SP);
    float4*   sbox  = reinterpret_cast<float4*>(dynsmem + OFF_BOX);
    unsigned* smask = reinterpret_cast<unsigned*>(dynsmem + OFF_MASK);
    int*      scnt  = reinterpret_cast<int*>(dynsmem + OFF_CNT);

    const int blk  = blockIdx.x + blockOff;
    const int b    = blk >> 4;              // 16 blocks per batch
    const int part = blk & 15;
    const int t    = threadIdx.x;
    const int q    = t >> 2;                // query slot 0..127
    const int seg  = t & 3;                 // lane within quad

    const float4* gs = g_sorted + (size_t)b * NS;
    for (int i = t; i < NS; i += KNN_THREADS) sp[i] = gs[i];
    if (t < QPB) scnt[t] = 0;
    __syncthreads();

    // word AABBs (one thread per word)
    if (t < 64) {
        const int jb = PAD + (t << 5);
        float4 p0 = sp[jb];
        float mnx = p0.x, mxx = p0.x, mny = p0.y, mxy = p0.y, mnz = p0.z, mxz = p0.z;
#pragma unroll 4
        for (int i = 1; i < 32; i++) {
            float4 p = sp[jb + i];
            mnx = fminf(mnx, p.x); mxx = fmaxf(mxx, p.x);
            mny = fminf(mny, p.y); mxy = fmaxf(mxy, p.y);
            mnz = fminf(mnz, p.z); mxz = fmaxf(mxz, p.z);
        }
        sbox[(t << 1)]     = make_float4(mnx, mny, mnz, 0.f);
        sbox[(t << 1) + 1] = make_float4(mxx, mxy, mxz, 0.f);
    }
    __syncthreads();
    // ---- barrier-free from here (all cross-lane comms are in-warp) ----

    const int rank = (part << 7) + q;
    const int ic   = PAD + rank;
    const float4 me = sp[ic];

    // ---- A: t0 = exact 16th of +-24 window, split 12 candidates per lane ----
    float dk[KK];
#pragma unroll
    for (int k = 0; k < KK; k++) dk[k] = 3.0e38f;
    {
        const int s0  = (seg & 1) * 12;
        const int dir = (seg & 2) ? 1 : -1;
#pragma unroll 2
        for (int k2 = 1; k2 <= 12; k2++) {
            int idx = ic + dir * (s0 + k2);
            idx = min(max(idx, 0), NS - 1);
            float4 p = sp[idx];
            float dx = me.x - p.x, dy = me.y - p.y, dz = me.z - p.z;
            float d2 = fmaf(dx, dx, fmaf(dy, dy, dz * dz));
            ins16(dk, d2);
        }
    }
    merge16(dk, 1);
    merge16(dk, 2);
    const float t0  = dk[KK - 1];
    const float t0b = t0 * 1.0001f;     // box-test slack absorbs fp rounding

    // ---- B: AABB-culled slice build. reg word g16 packs 4 gw-bytes ----
    const int mrow = t * MSTR;
#pragma unroll 1
    for (int g16 = 0; g16 < 16; g16++) {
        unsigned wreg = 0u;
#pragma unroll
        for (int bb = 0; bb < 4; bb++) {
            const int gw = (g16 << 2) + bb;
            float4 bmn = sbox[(gw << 1)];
            float4 bmx = sbox[(gw << 1) + 1];
            float ex = fmaxf(fmaxf(bmn.x - me.x, me.x - bmx.x), 0.f);
            float ey = fmaxf(fmaxf(bmn.y - me.y, me.y - bmx.y), 0.f);
            float ez = fmaxf(fmaxf(bmn.z - me.z, me.z - bmx.z), 0.f);
            float lb = fmaf(ex, ex, fmaf(ey, ey, ez * ez));
            if (lb <= t0b) {    // quad-uniform predicate (4 lanes identical)
                const float4* cp = sp + PAD + (gw << 5) + (seg << 3);
                unsigned byte = 0u;
#pragma unroll
                for (int u = 0; u < 8; u++) {
                    float4 p = cp[u];
                    float dx = me.x - p.x, dy = me.y - p.y, dz = me.z - p.z;
                    float d2 = fmaf(dx, dx, fmaf(dy, dy, dz * dz));
                    byte |= (d2 <= t0) ? (1u << u) : 0u;
                }
                wreg |= byte << (bb << 3);
            }
        }
        smask[mrow + g16] = wreg;
    }
    // clear self bit (owned by lane seg == (rank>>3)&3)
    if (seg == ((rank >> 3) & 3))
        smask[mrow + (rank >> 7)] &= ~(1u << ((((rank >> 5) & 3) << 3) + (rank & 7)));

    // ---- C: partial top-16 over own bits; shuffle-merge -> exact tau ----
    float sk[KK];
#pragma unroll
    for (int k = 0; k < KK; k++) sk[k] = 3.0e38f;
#pragma unroll 1
    for (int g16 = 0; g16 < 16; g16++) {
        unsigned bits = smask[mrow + g16];
        while (bits) {
            int u2 = __ffs(bits) - 1;
            bits &= bits - 1;
            int cand = ((g16 << 2) + (u2 >> 3)) * 32 + (seg << 3) + (u2 & 7);
            float4 p = sp[PAD + cand];
            float dx = me.x - p.x, dy = me.y - p.y, dz = me.z - p.z;
            float d2 = fmaf(dx, dx, fmaf(dy, dy, dz * dz));
            ins16(sk, d2);
        }
    }
    merge16(sk, 1);
    merge16(sk, 2);
    const float tau = sk[KK - 1];

    // ---- E: emit own bits with d2 <= tau via atomic slot assignment ----
    const int gbase = b * NN;
    int* orow = g_idx + (size_t)(gbase + __float_as_int(me.w)) * KK;
#pragma unroll 1
    for (int g16 = 0; g16 < 16; g16++) {
        unsigned bits = smask[mrow + g16];
        while (bits) {
            int u2 = __ffs(bits) - 1;
            bits &= bits - 1;
            int cand = ((g16 << 2) + (u2 >> 3)) * 32 + (seg << 3) + (u2 & 7);
            float4 p = sp[PAD + cand];
            float dx = me.x - p.x, dy = me.y - p.y, dz = me.z - p.z;
            float d2 = fmaf(dx, dx, fmaf(dy, dy, dz * dz));
            if (d2 <= tau) {
                int pos = atomicAdd(&scnt[q], 1);
                if (pos < KK) orow[pos] = gbase + __float_as_int(p.w);
            }
        }
    }
    __syncwarp();

    // safety fill (ties/degenerate; normally cnt >= 16)
    if (seg == 0) {
        int c = min(scnt[q], KK);
        if (c < KK) {
            int f = (c > 0) ? orow[0] : gbase;
            for (int k = c; k < KK; k++) orow[k] = f;
        }
    }
}

// ---------------------------------------------------------------------------
// Kernel 2: per-node transforms. a = x@(W1-W2)+b_e, c = x@W2, s = relu(x@Wn+bn)
// ---------------------------------------------------------------------------
__global__ __launch_bounds__(128) void transform_kernel(
    const float* __restrict__ x,
    const float* __restrict__ We,
    const float* __restrict__ be,
    const float* __restrict__ Wn,
    const float* __restrict__ bn)
{
    __shared__ float s_wd[FIN * FOUT];
    __shared__ float s_w2[FIN * FOUT];
    __shared__ float s_wn[FIN * FOUT];
    __shared__ float s_be[FOUT];
    __shared__ float s_bn[FOUT];

    const int tid = threadIdx.x;
    for (int t = tid; t < FIN * FOUT; t += 128) {
        float w2 = We[FIN * FOUT + t];
        s_w2[t] = w2;
        s_wd[t] = We[t] - w2;
        s_wn[t] = Wn[t];
    }
    if (tid < FOUT) { s_be[tid] = be[tid]; s_bn[tid] = bn[tid]; }
    __syncthreads();

    const int node = blockIdx.x * 128 + tid;

    float xr[FIN];
#pragma unroll
    for (int r = 0; r < FIN; r += 4) {
        float4 v = *reinterpret_cast<const float4*>(x + (size_t)node * FIN + r);
        xr[r] = v.x; xr[r + 1] = v.y; xr[r + 2] = v.z; xr[r + 3] = v.w;
    }

    for (int f0 = 0; f0 < FOUT; f0 += 4) {
        float a0 = s_be[f0], a1 = s_be[f0 + 1], a2 = s_be[f0 + 2], a3 = s_be[f0 + 3];
        float c0 = 0.f, c1 = 0.f, c2 = 0.f, c3 = 0.f;
        float k0 = s_bn[f0], k1 = s_bn[f0 + 1], k2 = s_bn[f0 + 2], k3 = s_bn[f0 + 3];
#pragma unroll
        for (int r = 0; r < FIN; r++) {
            float xv = xr[r];
            float4 wd = *reinterpret_cast<const float4*>(&s_wd[r * FOUT + f0]);
            float4 w2 = *reinterpret_cast<const float4*>(&s_w2[r * FOUT + f0]);
            float4 wn = *reinterpret_cast<const float4*>(&s_wn[r * FOUT + f0]);
            a0 = fmaf(xv, wd.x, a0); a1 = fmaf(xv, wd.y, a1);
            a2 = fmaf(xv, wd.z, a2); a3 = fmaf(xv, wd.w, a3);
            c0 = fmaf(xv, w2.x, c0); c1 = fmaf(xv, w2.y, c1);
            c2 = fmaf(xv, w2.z, c2); c3 = fmaf(xv, w2.w, c3);
            k0 = fmaf(xv, wn.x, k0); k1 = fmaf(xv, wn.y, k1);
            k2 = fmaf(xv, wn.z, k2); k3 = fmaf(xv, wn.w, k3);
        }
        size_t o = (size_t)node * FOUT + f0;
        *reinterpret_cast<float4*>(&g_a[o]) = make_float4(a0, a1, a2, a3);
        *reinterpret_cast<float4*>(&g_c[o]) = make_float4(c0, c1, c2, c3);
        *reinterpret_cast<float4*>(&g_s[o]) = make_float4(fmaxf(k0, 0.f), fmaxf(k1, 0.f),
                                                          fmaxf(k2, 0.f), fmaxf(k3, 0.f));
    }
}

// ---------------------------------------------------------------------------
// Kernel 3: aggregation, float4 per thread (4 features).
// ---------------------------------------------------------------------------
__global__ __launch_bounds__(256) void aggregate_kernel(float* __restrict__ out) {
    const int gid = blockIdx.x * 256 + threadIdx.x;
    const int i  = gid >> 4;
    const int f4 = (gid & 15) << 2;

    const int4* r4 = reinterpret_cast<const int4*>(g_idx + (size_t)i * KK);
    int4 j0 = r4[0], j1 = r4[1], j2 = r4[2], j3 = r4[3];
    int jj[KK] = { j0.x, j0.y, j0.z, j0.w, j1.x, j1.y, j1.z, j1.w,
                   j2.x, j2.y, j2.z, j2.w, j3.x, j3.y, j3.z, j3.w };

    float4 m = make_float4(-3.0e38f, -3.0e38f, -3.0e38f, -3.0e38f);
#pragma unroll
    for (int k = 0; k < KK; k++) {
        float4 v = *reinterpret_cast<const float4*>(&g_c[(size_t)jj[k] * FOUT + f4]);
        m.x = fmaxf(m.x, v.x); m.y = fmaxf(m.y, v.y);
        m.z = fmaxf(m.z, v.z); m.w = fmaxf(m.w, v.w);
    }

    const size_t o = (size_t)i * FOUT + f4;
    float4 a = *reinterpret_cast<const float4*>(&g_a[o]);
    float4 s = *reinterpret_cast<const float4*>(&g_s[o]);
    float4 r;
    r.x = fmaxf(m.x + a.x, 0.f) + s.x;
    r.y = fmaxf(m.y + a.y, 0.f) + s.y;
    r.z = fmaxf(m.z + a.z, 0.f) + s.z;
    r.w = fmaxf(m.w + a.w, 0.f) + s.w;
    *reinterpret_cast<float4*>(&out[o]) = r;
}

// ---------------------------------------------------------------------------
// knn split into 5 partial-grid launches (identical total work): matches the
// 8-launch layout where ncu reliably captured knn (R10) for direct profiling.
// ---------------------------------------------------------------------------
extern "C" void kernel_launch(void* const* d_in, const int* in_sizes, int n_in,
                              void* d_out, int out_size) {
    const float* x   = (const float*)d_in[0];
    const float* pos = (const float*)d_in[1];
    const float* We  = (const float*)d_in[2];
    const float* be  = (const float*)d_in[3];
    const float* Wn  = (const float*)d_in[4];
    const float* bn  = (const float*)d_in[5];
    float* out = (float*)d_out;

    cudaFuncSetAttribute(knn_kernel, cudaFuncAttributeMaxDynamicSharedMemorySize, KNN_SMEM);

    sort_kernel<<<BB, 1024>>>(pos);
    knn_kernel<<<104, KNN_THREADS, KNN_SMEM>>>(0);
    knn_kernel<<<104, KNN_THREADS, KNN_SMEM>>>(104);
    knn_kernel<<<104, KNN_THREADS, KNN_SMEM>>>(208);
    knn_kernel<<<104, KNN_THREADS, KNN_SMEM>>>(312);
    knn_kernel<<<96,  KNN_THREADS, KNN_SMEM>>>(416);
    transform_kernel<<<NPTS / 128, 128>>>(x, We, be, Wn, bn);
    aggregate_kernel<<<(NPTS * FOUT / 4) / 256, 256>>>(out);
}

// round 16
// speedup vs baseline: 2.9793x; 2.9793x over previous
#include <cuda_runtime.h>

#define BB   32
#define NN   2048
#define KK   16
#define FIN  32
#define FOUT 64
#define NPTS (BB * NN)          // 65536
#define PAD  4
#define NS   (NN + 2 * PAD)     // 2056
#define QPB  128                // queries per block
#define KNN_THREADS 512         // 4 lanes per query, in-warp quads
#define MSTR 17                 // padded per-thread mask stride (words)

// SMEM layout (bytes)
#define OFF_SP    0
#define OFF_BOX   (NS * 16)                    // 32896 : 64 boxes x 2 float4
#define OFF_MASK  (OFF_BOX + 64 * 32)          // 34944 : 512 threads x 17 words
#define OFF_CNT   (OFF_MASK + KNN_THREADS * MSTR * 4)   // 69760
#define KNN_SMEM  (OFF_CNT + QPB * 4)          // 70272

// Scratch (allocation-free rule: __device__ globals)
__device__ float4 g_sorted[BB * NS];
__device__ float  g_a[NPTS * FOUT];
__device__ float  g_c[NPTS * FOUT];
__device__ float  g_s[NPTS * FOUT];
__device__ int    g_idx[NPTS * KK];

// ---------------------------------------------------------------------------
__device__ __forceinline__ unsigned spread3(unsigned x) {
    x &= 0x3FF;
    x = (x | (x << 16)) & 0x030000FF;
    x = (x | (x << 8))  & 0x0300F00F;
    x = (x | (x << 4))  & 0x030C30C3;
    x = (x | (x << 2))  & 0x09249249;
    return x;
}

// ---------------------------------------------------------------------------
// Kernel 0: per-batch Morton sort (7 bits/dim). Bitonic on packed uint32 keys.
// ---------------------------------------------------------------------------
__global__ __launch_bounds__(1024) void sort_kernel(const float* __restrict__ pos) {
    __shared__ float4   spp[NN];
    __shared__ unsigned key[NN];
    __shared__ float    s_red[6][32];
    __shared__ float    s_bounds[6];

    const int b    = blockIdx.x;
    const int tid  = threadIdx.x;
    const int lane = tid & 31;
    const int wid  = tid >> 5;

    for (int i = tid; i < NN; i += 1024) {
        const float* p = pos + (size_t)(b * NN + i) * 3;
        spp[i] = make_float4(p[0], p[1], p[2], __int_as_float(i));
    }
    __syncthreads();

    float mn[3] = { 3e38f, 3e38f, 3e38f }, mx[3] = { -3e38f, -3e38f, -3e38f };
    for (int i = tid; i < NN; i += 1024) {
        float4 q = spp[i];
        mn[0] = fminf(mn[0], q.x); mx[0] = fmaxf(mx[0], q.x);
        mn[1] = fminf(mn[1], q.y); mx[1] = fmaxf(mx[1], q.y);
        mn[2] = fminf(mn[2], q.z); mx[2] = fmaxf(mx[2], q.z);
    }
#pragma unroll
    for (int o = 16; o; o >>= 1) {
#pragma unroll
        for (int d = 0; d < 3; d++) {
            mn[d] = fminf(mn[d], __shfl_xor_sync(0xFFFFFFFFu, mn[d], o));
            mx[d] = fmaxf(mx[d], __shfl_xor_sync(0xFFFFFFFFu, mx[d], o));
        }
    }
    if (lane == 0) {
#pragma unroll
        for (int d = 0; d < 3; d++) { s_red[d][wid] = mn[d]; s_red[3 + d][wid] = mx[d]; }
    }
    __syncthreads();
    if (tid < 32) {
        float v0 = s_red[0][tid], v1 = s_red[1][tid], v2 = s_red[2][tid];
        float v3 = s_red[3][tid], v4 = s_red[4][tid], v5 = s_red[5][tid];
#pragma unroll
        for (int o = 16; o; o >>= 1) {
            v0 = fminf(v0, __shfl_xor_sync(0xFFFFFFFFu, v0, o));
            v1 = fminf(v1, __shfl_xor_sync(0xFFFFFFFFu, v1, o));
            v2 = fminf(v2, __shfl_xor_sync(0xFFFFFFFFu, v2, o));
            v3 = fmaxf(v3, __shfl_xor_sync(0xFFFFFFFFu, v3, o));
            v4 = fmaxf(v4, __shfl_xor_sync(0xFFFFFFFFu, v4, o));
            v5 = fmaxf(v5, __shfl_xor_sync(0xFFFFFFFFu, v5, o));
        }
        if (tid == 0) {
            s_bounds[0] = v0; s_bounds[1] = v1; s_bounds[2] = v2;
            s_bounds[3] = 127.0f / fmaxf(v3 - v0, 1e-12f);
            s_bounds[4] = 127.0f / fmaxf(v4 - v1, 1e-12f);
            s_bounds[5] = 127.0f / fmaxf(v5 - v2, 1e-12f);
        }
    }
    __syncthreads();

    const float mnx = s_bounds[0], mny = s_bounds[1], mnz = s_bounds[2];
    const float sx = s_bounds[3], sy = s_bounds[4], sz = s_bounds[5];
    for (int i = tid; i < NN; i += 1024) {
        float4 q = spp[i];
        unsigned ux = (unsigned)min(max((int)((q.x - mnx) * sx), 0), 127);
        unsigned uy = (unsigned)min(max((int)((q.y - mny) * sy), 0), 127);
        unsigned uz = (unsigned)min(max((int)((q.z - mnz) * sz), 0), 127);
        unsigned code = spread3(ux) | (spread3(uy) << 1) | (spread3(uz) << 2);
        key[i] = (code << 11) | (unsigned)i;
    }

    for (int k = 2; k <= NN; k <<= 1) {
        for (int j = k >> 1; j > 0; j >>= 1) {
            __syncthreads();
            int l = ((tid & ~(j - 1)) << 1) | (tid & (j - 1));
            int p = l | j;
            unsigned A = key[l], Bv = key[p];
            bool asc = (l & k) == 0;
            if ((A > Bv) == asc) { key[l] = Bv; key[p] = A; }
        }
    }
    __syncthreads();

    float4* gs = g_sorted + (size_t)b * NS;
    for (int i = tid; i < NN; i += 1024) gs[PAD + i] = spp[key[i] & 0x7FF];
    if (tid < PAD) {
        gs[tid]            = make_float4(-1.0e30f, -1.0e30f, -1.0e30f, __int_as_float(0));
        gs[PAD + NN + tid] = make_float4( 1.0e30f,  1.0e30f,  1.0e30f, __int_as_float(0));
    }
}

// ---------------------------------------------------------------------------
__device__ __forceinline__ void ins16(float dk[KK], float v) {
#pragma unroll
    for (int k = 0; k < KK; k++) {
        float lo = fminf(dk[k], v);
        v = fmaxf(dk[k], v);
        dk[k] = lo;
    }
}

// Merge my ascending dk[16] with xor-partner's: keep 16 smallest, re-sorted.
__device__ __forceinline__ void merge16(float dk[KK], int lanemask) {
    float o[KK];
#pragma unroll
    for (int i = 0; i < KK; i++)
        o[i] = __shfl_xor_sync(0xFFFFFFFFu, dk[KK - 1 - i], lanemask);
#pragma unroll
    for (int i = 0; i < KK; i++) dk[i] = fminf(dk[i], o[i]);
#pragma unroll
    for (int d = 8; d >= 1; d >>= 1) {
#pragma unroll
        for (int i = 0; i < KK; i++) {
            if ((i & d) == 0) {
                float lo = fminf(dk[i], dk[i | d]);
                float hi = fmaxf(dk[i], dk[i | d]);
                dk[i] = lo; dk[i | d] = hi;
            }
        }
    }
}

// ---------------------------------------------------------------------------
// Kernel 1: exact kNN. 4 lanes per query (in-warp quad); barrier-free after
// setup. SINGLE 512-block launch (R14's 5-way split collapsed occupancy).
//  A) 48-candidate Morton window split 4-ways; shuffle-merge -> exact t0.
//  B) box tests distributed across quad lanes (1 box each, ballot-shared);
//     surviving words get the 4-lane branchless slice build.
//  C) walk own bits -> partial top-16; shuffle-merge -> exact tau.
//  E) walk again, emit d2<=tau via SMEM-atomic slots (max-pool order-free).
// ---------------------------------------------------------------------------
__global__ __launch_bounds__(KNN_THREADS) void knn_kernel() {
    extern __shared__ unsigned char dynsmem[];
    float4*   sp    = reinterpret_cast<float4*>(dynsmem + OFF_SP);
    float4*   sbox  = reinterpret_cast<float4*>(dynsmem + OFF_BOX);
    unsigned* smask = reinterpret_cast<unsigned*>(dynsmem + OFF_MASK);
    int*      scnt  = reinterpret_cast<int*>(dynsmem + OFF_CNT);

    const int blk  = blockIdx.x;
    const int b    = blk >> 4;              // 16 blocks per batch
    const int part = blk & 15;
    const int t    = threadIdx.x;
    const int lane = t & 31;
    const int q    = t >> 2;                // query slot 0..127
    const int seg  = t & 3;                 // lane within quad

    const float4* gs = g_sorted + (size_t)b * NS;
    for (int i = t; i < NS; i += KNN_THREADS) sp[i] = gs[i];
    if (t < QPB) scnt[t] = 0;
    __syncthreads();

    // word AABBs (one thread per word)
    if (t < 64) {
        const int jb = PAD + (t << 5);
        float4 p0 = sp[jb];
        float mnx = p0.x, mxx = p0.x, mny = p0.y, mxy = p0.y, mnz = p0.z, mxz = p0.z;
#pragma unroll 4
        for (int i = 1; i < 32; i++) {
            float4 p = sp[jb + i];
            mnx = fminf(mnx, p.x); mxx = fmaxf(mxx, p.x);
            mny = fminf(mny, p.y); mxy = fmaxf(mxy, p.y);
            mnz = fminf(mnz, p.z); mxz = fmaxf(mxz, p.z);
        }
        sbox[(t << 1)]     = make_float4(mnx, mny, mnz, 0.f);
        sbox[(t << 1) + 1] = make_float4(mxx, mxy, mxz, 0.f);
    }
    __syncthreads();
    // ---- barrier-free from here (all cross-lane comms are in-warp) ----

    const int rank = (part << 7) + q;
    const int ic   = PAD + rank;
    const float4 me = sp[ic];

    // ---- A: t0 = exact 16th of +-24 window, split 12 candidates per lane ----
    float dk[KK];
#pragma unroll
    for (int k = 0; k < KK; k++) dk[k] = 3.0e38f;
    {
        const int s0  = (seg & 1) * 12;
        const int dir = (seg & 2) ? 1 : -1;
#pragma unroll 2
        for (int k2 = 1; k2 <= 12; k2++) {
            int idx = ic + dir * (s0 + k2);
            idx = min(max(idx, 0), NS - 1);
            float4 p = sp[idx];
            float dx = me.x - p.x, dy = me.y - p.y, dz = me.z - p.z;
            float d2 = fmaf(dx, dx, fmaf(dy, dy, dz * dz));
            ins16(dk, d2);
        }
    }
    merge16(dk, 1);
    merge16(dk, 2);
    const float t0  = dk[KK - 1];
    const float t0b = t0 * 1.0001f;     // box-test slack absorbs fp rounding

    // ---- B: lane-distributed box tests + slice build for survivors ----
    const int mrow = t * MSTR;
#pragma unroll 1
    for (int g16 = 0; g16 < 16; g16++) {
        // my lane tests box (g16<<2)+seg only; share verdicts via ballot
        const int gwme = (g16 << 2) + seg;
        float4 bmn = sbox[(gwme << 1)];
        float4 bmx = sbox[(gwme << 1) + 1];
        float ex = fmaxf(fmaxf(bmn.x - me.x, me.x - bmx.x), 0.f);
        float ey = fmaxf(fmaxf(bmn.y - me.y, me.y - bmx.y), 0.f);
        float ez = fmaxf(fmaxf(bmn.z - me.z, me.z - bmx.z), 0.f);
        float lb = fmaf(ex, ex, fmaf(ey, ey, ez * ez));
        unsigned vote = __ballot_sync(0xFFFFFFFFu, lb <= t0b);
        unsigned quadmask = (vote >> (lane & ~3)) & 0xFu;   // 4 verdicts of my quad

        unsigned wreg = 0u;
        while (quadmask) {                  // usually 0-1 iterations
            int bb = __ffs(quadmask) - 1;
            quadmask &= quadmask - 1;
            const int gw = (g16 << 2) + bb;
            const float4* cp = sp + PAD + (gw << 5) + (seg << 3);
            unsigned byte = 0u;
#pragma unroll
            for (int u = 0; u < 8; u++) {
                float4 p = cp[u];
                float dx = me.x - p.x, dy = me.y - p.y, dz = me.z - p.z;
                float d2 = fmaf(dx, dx, fmaf(dy, dy, dz * dz));
                byte |= (d2 <= t0) ? (1u << u) : 0u;
            }
            wreg |= byte << (bb << 3);
        }
        smask[mrow + g16] = wreg;
    }
    // clear self bit (owned by lane seg == (rank>>3)&3)
    if (seg == ((rank >> 3) & 3))
        smask[mrow + (rank >> 7)] &= ~(1u << ((((rank >> 5) & 3) << 3) + (rank & 7)));

    // ---- C: partial top-16 over own bits; shuffle-merge -> exact tau ----
    float sk[KK];
#pragma unroll
    for (int k = 0; k < KK; k++) sk[k] = 3.0e38f;
#pragma unroll 1
    for (int g16 = 0; g16 < 16; g16++) {
        unsigned bits = smask[mrow + g16];
        while (bits) {
            int u2 = __ffs(bits) - 1;
            bits &= bits - 1;
            int cand = ((g16 << 2) + (u2 >> 3)) * 32 + (seg << 3) + (u2 & 7);
            float4 p = sp[PAD + cand];
            float dx = me.x - p.x, dy = me.y - p.y, dz = me.z - p.z;
            float d2 = fmaf(dx, dx, fmaf(dy, dy, dz * dz));
            ins16(sk, d2);
        }
    }
    merge16(sk, 1);
    merge16(sk, 2);
    const float tau = sk[KK - 1];

    // ---- E: emit own bits with d2 <= tau via atomic slot assignment ----
    const int gbase = b * NN;
    int* orow = g_idx + (size_t)(gbase + __float_as_int(me.w)) * KK;
#pragma unroll 1
    for (int g16 = 0; g16 < 16; g16++) {
        unsigned bits = smask[mrow + g16];
        while (bits) {
            int u2 = __ffs(bits) - 1;
            bits &= bits - 1;
            int cand = ((g16 << 2) + (u2 >> 3)) * 32 + (seg << 3) + (u2 & 7);
            float4 p = sp[PAD + cand];
            float dx = me.x - p.x, dy = me.y - p.y, dz = me.z - p.z;
            float d2 = fmaf(dx, dx, fmaf(dy, dy, dz * dz));
            if (d2 <= tau) {
                int pos = atomicAdd(&scnt[q], 1);
                if (pos < KK) orow[pos] = gbase + __float_as_int(p.w);
            }
        }
    }
    __syncwarp();

    // safety fill (ties/degenerate; normally cnt >= 16)
    if (seg == 0) {
        int c = min(scnt[q], KK);
        if (c < KK) {
            int f = (c > 0) ? orow[0] : gbase;
            for (int k = c; k < KK; k++) orow[k] = f;
        }
    }
}

// ---------------------------------------------------------------------------
// Kernel 2: per-node transforms. a = x@(W1-W2)+b_e, c = x@W2, s = relu(x@Wn+bn)
// ---------------------------------------------------------------------------
__global__ __launch_bounds__(128) void transform_kernel(
    const float* __restrict__ x,
    const float* __restrict__ We,
    const float* __restrict__ be,
    const float* __restrict__ Wn,
    const float* __restrict__ bn)
{
    __shared__ float s_wd[FIN * FOUT];
    __shared__ float s_w2[FIN * FOUT];
    __shared__ float s_wn[FIN * FOUT];
    __shared__ float s_be[FOUT];
    __shared__ float s_bn[FOUT];

    const int tid = threadIdx.x;
    for (int t = tid; t < FIN * FOUT; t += 128) {
        float w2 = We[FIN * FOUT + t];
        s_w2[t] = w2;
        s_wd[t] = We[t] - w2;
        s_wn[t] = Wn[t];
    }
    if (tid < FOUT) { s_be[tid] = be[tid]; s_bn[tid] = bn[tid]; }
    __syncthreads();

    const int node = blockIdx.x * 128 + tid;

    float xr[FIN];
#pragma unroll
    for (int r = 0; r < FIN; r += 4) {
        float4 v = *reinterpret_cast<const float4*>(x + (size_t)node * FIN + r);
        xr[r] = v.x; xr[r + 1] = v.y; xr[r + 2] = v.z; xr[r + 3] = v.w;
    }

    for (int f0 = 0; f0 < FOUT; f0 += 4) {
        float a0 = s_be[f0], a1 = s_be[f0 + 1], a2 = s_be[f0 + 2], a3 = s_be[f0 + 3];
        float c0 = 0.f, c1 = 0.f, c2 = 0.f, c3 = 0.f;
        float k0 = s_bn[f0], k1 = s_bn[f0 + 1], k2 = s_bn[f0 + 2], k3 = s_bn[f0 + 3];
#pragma unroll
        for (int r = 0; r < FIN; r++) {
            float xv = xr[r];
            float4 wd = *reinterpret_cast<const float4*>(&s_wd[r * FOUT + f0]);
            float4 w2 = *reinterpret_cast<const float4*>(&s_w2[r * FOUT + f0]);
            float4 wn = *reinterpret_cast<const float4*>(&s_wn[r * FOUT + f0]);
            a0 = fmaf(xv, wd.x, a0); a1 = fmaf(xv, wd.y, a1);
            a2 = fmaf(xv, wd.z, a2); a3 = fmaf(xv, wd.w, a3);
            c0 = fmaf(xv, w2.x, c0); c1 = fmaf(xv, w2.y, c1);
            c2 = fmaf(xv, w2.z, c2); c3 = fmaf(xv, w2.w, c3);
            k0 = fmaf(xv, wn.x, k0); k1 = fmaf(xv, wn.y, k1);
            k2 = fmaf(xv, wn.z, k2); k3 = fmaf(xv, wn.w, k3);
        }
        size_t o = (size_t)node * FOUT + f0;
        *reinterpret_cast<float4*>(&g_a[o]) = make_float4(a0, a1, a2, a3);
        *reinterpret_cast<float4*>(&g_c[o]) = make_float4(c0, c1, c2, c3);
        *reinterpret_cast<float4*>(&g_s[o]) = make_float4(fmaxf(k0, 0.f), fmaxf(k1, 0.f),
                                                          fmaxf(k2, 0.f), fmaxf(k3, 0.f));
    }
}

// ---------------------------------------------------------------------------
// Kernel 3: aggregation, float4 per thread (4 features).
// ---------------------------------------------------------------------------
__global__ __launch_bounds__(256) void aggregate_kernel(float* __restrict__ out) {
    const int gid = blockIdx.x * 256 + threadIdx.x;
    const int i  = gid >> 4;
    const int f4 = (gid & 15) << 2;

    const int4* r4 = reinterpret_cast<const int4*>(g_idx + (size_t)i * KK);
    int4 j0 = r4[0], j1 = r4[1], j2 = r4[2], j3 = r4[3];
    int jj[KK] = { j0.x, j0.y, j0.z, j0.w, j1.x, j1.y, j1.z, j1.w,
                   j2.x, j2.y, j2.z, j2.w, j3.x, j3.y, j3.z, j3.w };

    float4 m = make_float4(-3.0e38f, -3.0e38f, -3.0e38f, -3.0e38f);
#pragma unroll
    for (int k = 0; k < KK; k++) {
        float4 v = *reinterpret_cast<const float4*>(&g_c[(size_t)jj[k] * FOUT + f4]);
        m.x = fmaxf(m.x, v.x); m.y = fmaxf(m.y, v.y);
        m.z = fmaxf(m.z, v.z); m.w = fmaxf(m.w, v.w);
    }

    const size_t o = (size_t)i * FOUT + f4;
    float4 a = *reinterpret_cast<const float4*>(&g_a[o]);
    float4 s = *reinterpret_cast<const float4*>(&g_s[o]);
    float4 r;
    r.x = fmaxf(m.x + a.x, 0.f) + s.x;
    r.y = fmaxf(m.y + a.y, 0.f) + s.y;
    r.z = fmaxf(m.z + a.z, 0.f) + s.z;
    r.w = fmaxf(m.w + a.w, 0.f) + s.w;
    *reinterpret_cast<float4*>(&out[o]) = r;
}

// ---------------------------------------------------------------------------
extern "C" void kernel_launch(void* const* d_in, const int* in_sizes, int n_in,
                              void* d_out, int out_size) {
    const float* x   = (const float*)d_in[0];
    const float* pos = (const float*)d_in[1];
    const float* We  = (const float*)d_in[2];
    const float* be  = (const float*)d_in[3];
    const float* Wn  = (const float*)d_in[4];
    const float* bn  = (const float*)d_in[5];
    float* out = (float*)d_out;

    cudaFuncSetAttribute(knn_kernel, cudaFuncAttributeMaxDynamicSharedMemorySize, KNN_SMEM);

    sort_kernel<<<BB, 1024>>>(pos);
    knn_kernel<<<BB * 16, KNN_THREADS, KNN_SMEM>>>();
    transform_kernel<<<NPTS / 128, 128>>>(x, We, be, Wn, bn);
    aggregate_kernel<<<(NPTS * FOUT / 4) / 256, 256>>>(out);
}